// round 2
// baseline (speedup 1.0000x reference)
#include <cuda_runtime.h>
#include <math.h>

// Problem dims (fixed)
#define Tn 16384   // B*S tokens
#define Dn 1024
#define Hn 2048
#define An 128
#define En 8
#define Sn 2048
#define Bn 8

// ---------------- scratch (device globals; no allocation allowed) -------------
__device__ float g_up[(size_t)Tn * Hn];       // up projection
__device__ float g_hidden[(size_t)Tn * Hn];   // silu(gate)*up
__device__ float g_pre[(size_t)Tn * An];      // x @ w_pre^T
__device__ float g_ain[(size_t)Tn * An];      // LN(pre)
__device__ float g_aout[(size_t)Tn * An];     // LN(hidden @ w_post^T) (in-place LN)
__device__ float g_adapt[(size_t)Tn * An];    // 0.1 * (aw @ adapt_in)
__device__ float g_aexp[(size_t)Tn * An];     // 0.1 * LN(pre @ w_exp[sel]^T)
__device__ float g_aw[(size_t)Bn * Sn * Sn];  // silu(clip(ain @ aout^T))
__device__ float g_wM[Dn * An];               // w_out @ w_eproj
__device__ float g_wda[Dn * An];              // w_down @ w_aproj

__device__ __forceinline__ float silu_f(float x) { return x / (1.f + expf(-x)); }

// ---------------- NT GEMM: C[m,n] = sum over (up to 3) segments A[m,:]·B[n,:] --
// A: [M,Kseg] row-major, B: [N,Kseg] row-major. Tile 128x128x16, 256 thr, 8x8.
// EPI: 0=none, 1=silu(acc)*aux, 2=silu(clip(acc,-5,5)), 3=0.1*acc
template <int EPI>
__global__ __launch_bounds__(256, 2)
void gemm_nt(const float* __restrict__ A0, const float* __restrict__ B0, int K0,
             const float* __restrict__ A1, const float* __restrict__ B1, int K1,
             const float* __restrict__ A2, const float* __restrict__ B2, int K2,
             float* __restrict__ C, int N,
             const float* __restrict__ aux,
             long sA, long sB, long sC)
{
    __shared__ float As[16][128];
    __shared__ float Bs[16][128];
    const int bm = blockIdx.y << 7;
    const int bn = blockIdx.x << 7;
    const long z = blockIdx.z;
    const int tid = threadIdx.x;
    const int tx = tid & 15, ty = tid >> 4;
    const int lr = tid >> 2, lc = (tid & 3) << 2;

    float acc[8][8];
#pragma unroll
    for (int i = 0; i < 8; i++)
#pragma unroll
        for (int j = 0; j < 8; j++) acc[i][j] = 0.f;

#pragma unroll 1
    for (int seg = 0; seg < 3; ++seg) {
        const float* A = (seg == 0) ? A0 + z * sA : ((seg == 1) ? A1 : A2);
        const float* B = (seg == 0) ? B0 + z * sB : ((seg == 1) ? B1 : B2);
        const int K = (seg == 0) ? K0 : ((seg == 1) ? K1 : K2);
        for (int kt = 0; kt < K; kt += 16) {
#pragma unroll
            for (int r = 0; r < 2; r++) {
                int row = lr + (r << 6);
                float4 va = *(const float4*)(A + (size_t)(bm + row) * K + kt + lc);
                As[lc + 0][row] = va.x; As[lc + 1][row] = va.y;
                As[lc + 2][row] = va.z; As[lc + 3][row] = va.w;
                float4 vb = *(const float4*)(B + (size_t)(bn + row) * K + kt + lc);
                Bs[lc + 0][row] = vb.x; Bs[lc + 1][row] = vb.y;
                Bs[lc + 2][row] = vb.z; Bs[lc + 3][row] = vb.w;
            }
            __syncthreads();
#pragma unroll
            for (int k = 0; k < 16; k++) {
                float a[8], b[8];
#pragma unroll
                for (int i = 0; i < 8; i++) a[i] = As[k][(ty << 3) + i];
#pragma unroll
                for (int j = 0; j < 8; j++) b[j] = Bs[k][(tx << 3) + j];
#pragma unroll
                for (int i = 0; i < 8; i++)
#pragma unroll
                    for (int j = 0; j < 8; j++)
                        acc[i][j] = fmaf(a[i], b[j], acc[i][j]);
            }
            __syncthreads();
        }
    }

    float* Cz = C + z * sC;
#pragma unroll
    for (int i = 0; i < 8; i++) {
        size_t off = (size_t)(bm + (ty << 3) + i) * N + bn + (tx << 3);
        float v[8];
#pragma unroll
        for (int j = 0; j < 8; j++) {
            float t = acc[i][j];
            if (EPI == 1) { t = silu_f(t) * aux[off + j]; }
            else if (EPI == 2) { t = fminf(fmaxf(t, -5.f), 5.f); t = silu_f(t); }
            else if (EPI == 3) { t *= 0.1f; }
            v[j] = t;
        }
        *(float4*)(Cz + off)     = make_float4(v[0], v[1], v[2], v[3]);
        *(float4*)(Cz + off + 4) = make_float4(v[4], v[5], v[6], v[7]);
    }
}

// ---------------- NN GEMM: C[m,n] = sum_k A[m,k]*B[k,n] -----------------------
// A: [M,K] row-major, B: [K,N] row-major. Same tiling. EPI: 0=none, 3=0.1*acc.
template <int EPI>
__global__ __launch_bounds__(256, 2)
void gemm_nn(const float* __restrict__ A, const float* __restrict__ B,
             float* __restrict__ C, int N, int K,
             long sA, long sB, long sC)
{
    __shared__ float As[16][128];
    __shared__ float Bs[16][128];
    const int bm = blockIdx.y << 7;
    const int bn = blockIdx.x << 7;
    const long z = blockIdx.z;
    const int tid = threadIdx.x;
    const int tx = tid & 15, ty = tid >> 4;
    const int lr = tid >> 2, lc = (tid & 3) << 2;   // A loader
    const int br = tid >> 5, bc = (tid & 31) << 2;  // B loader

    const float* Az = A + z * sA;
    const float* Bz = B + z * sB;

    float acc[8][8];
#pragma unroll
    for (int i = 0; i < 8; i++)
#pragma unroll
        for (int j = 0; j < 8; j++) acc[i][j] = 0.f;

    for (int kt = 0; kt < K; kt += 16) {
#pragma unroll
        for (int r = 0; r < 2; r++) {
            int row = lr + (r << 6);
            float4 va = *(const float4*)(Az + (size_t)(bm + row) * K + kt + lc);
            As[lc + 0][row] = va.x; As[lc + 1][row] = va.y;
            As[lc + 2][row] = va.z; As[lc + 3][row] = va.w;
            int krow = br + (r << 3);
            float4 vb = *(const float4*)(Bz + (size_t)(kt + krow) * N + bn + bc);
            *(float4*)&Bs[krow][bc] = vb;
        }
        __syncthreads();
#pragma unroll
        for (int k = 0; k < 16; k++) {
            float a[8], b[8];
#pragma unroll
            for (int i = 0; i < 8; i++) a[i] = As[k][(ty << 3) + i];
#pragma unroll
            for (int j = 0; j < 8; j++) b[j] = Bs[k][(tx << 3) + j];
#pragma unroll
            for (int i = 0; i < 8; i++)
#pragma unroll
                for (int j = 0; j < 8; j++)
                    acc[i][j] = fmaf(a[i], b[j], acc[i][j]);
        }
        __syncthreads();
    }

    float* Cz = C + z * sC;
#pragma unroll
    for (int i = 0; i < 8; i++) {
        size_t off = (size_t)(bm + (ty << 3) + i) * N + bn + (tx << 3);
        float v[8];
#pragma unroll
        for (int j = 0; j < 8; j++) {
            float t = acc[i][j];
            if (EPI == 3) t *= 0.1f;
            v[j] = t;
        }
        *(float4*)(Cz + off)     = make_float4(v[0], v[1], v[2], v[3]);
        *(float4*)(Cz + off + 4) = make_float4(v[4], v[5], v[6], v[7]);
    }
}

// ---------------- LayerNorm over last dim (A=128), one token per block --------
__global__ void ln128(const float* __restrict__ in, float* __restrict__ out,
                      const float* __restrict__ g, const float* __restrict__ b)
{
    __shared__ float red[128];
    const int tok = blockIdx.x, tid = threadIdx.x;
    float x = in[(size_t)tok * 128 + tid];
    red[tid] = x; __syncthreads();
#pragma unroll
    for (int s = 64; s > 0; s >>= 1) { if (tid < s) red[tid] += red[tid + s]; __syncthreads(); }
    float mean = red[0] * (1.f / 128.f);
    __syncthreads();
    float d = x - mean;
    red[tid] = d * d; __syncthreads();
#pragma unroll
    for (int s = 64; s > 0; s >>= 1) { if (tid < s) red[tid] += red[tid + s]; __syncthreads(); }
    float var = red[0] * (1.f / 128.f);
    out[(size_t)tok * 128 + tid] = d * rsqrtf(var + 1e-5f) * g[tid] + b[tid];
}

// ---------------- expert path: last selected expert, matvec + LN, 0.1 scale ---
__global__ void expert128(const float* __restrict__ pre, const float* __restrict__ ew,
                          const float* __restrict__ w_exp, const float* __restrict__ eg,
                          const float* __restrict__ eb, float* __restrict__ out)
{
    __shared__ float sp[128];
    __shared__ float red[128];
    const int tok = blockIdx.x, tid = threadIdx.x;
    int sel = -1;
#pragma unroll
    for (int i = 0; i < 8; i++)
        if (ew[(size_t)tok * 8 + i] > 0.f) sel = i;   // later experts win
    if (sel < 0) { out[(size_t)tok * 128 + tid] = 0.f; return; }  // uniform per block

    sp[tid] = pre[(size_t)tok * 128 + tid];
    __syncthreads();
    const float* wr = w_exp + ((size_t)sel * 128 + tid) * 128;  // row c=tid of w_exp[sel]
    float acc = 0.f;
#pragma unroll 8
    for (int a = 0; a < 128; a++) acc = fmaf(sp[a], wr[a], acc);

    red[tid] = acc; __syncthreads();
#pragma unroll
    for (int s = 64; s > 0; s >>= 1) { if (tid < s) red[tid] += red[tid + s]; __syncthreads(); }
    float mean = red[0] * (1.f / 128.f);
    __syncthreads();
    float d = acc - mean;
    red[tid] = d * d; __syncthreads();
#pragma unroll
    for (int s = 64; s > 0; s >>= 1) { if (tid < s) red[tid] += red[tid + s]; __syncthreads(); }
    float var = red[0] * (1.f / 128.f);
    out[(size_t)tok * 128 + tid] =
        0.1f * (d * rsqrtf(var + 1e-5f) * eg[sel * 128 + tid] + eb[sel * 128 + tid]);
}

// ---------------- launch ------------------------------------------------------
extern "C" void kernel_launch(void* const* d_in, const int* in_sizes, int n_in,
                              void* d_out, int out_size)
{
    const float* x       = (const float*)d_in[0];
    const float* ew      = (const float*)d_in[1];
    const float* w_up    = (const float*)d_in[2];
    const float* w_gate  = (const float*)d_in[3];
    const float* w_down  = (const float*)d_in[4];
    const float* w_pre   = (const float*)d_in[5];
    const float* w_post  = (const float*)d_in[6];
    const float* an_g    = (const float*)d_in[7];
    const float* an_b    = (const float*)d_in[8];
    const float* w_aproj = (const float*)d_in[9];
    const float* w_exp   = (const float*)d_in[10];
    const float* eln_g   = (const float*)d_in[11];
    const float* eln_b   = (const float*)d_in[12];
    const float* w_eproj = (const float*)d_in[13];
    const float* w_out   = (const float*)d_in[14];
    float* out = (float*)d_out;

    float *up, *hid, *pre, *ain, *aout, *adp, *aex, *aw, *wM, *wda;
    cudaGetSymbolAddress((void**)&up,   g_up);
    cudaGetSymbolAddress((void**)&hid,  g_hidden);
    cudaGetSymbolAddress((void**)&pre,  g_pre);
    cudaGetSymbolAddress((void**)&ain,  g_ain);
    cudaGetSymbolAddress((void**)&aout, g_aout);
    cudaGetSymbolAddress((void**)&adp,  g_adapt);
    cudaGetSymbolAddress((void**)&aex,  g_aexp);
    cudaGetSymbolAddress((void**)&aw,   g_aw);
    cudaGetSymbolAddress((void**)&wM,   g_wM);
    cudaGetSymbolAddress((void**)&wda,  g_wda);

    const dim3 blk(256);

    // 1. pre = x @ w_pre^T                       [16384,128]
    gemm_nt<0><<<dim3(1, 128, 1), blk>>>(x, w_pre, Dn, nullptr, nullptr, 0,
                                         nullptr, nullptr, 0, pre, An, nullptr, 0, 0, 0);
    // 2. adapt_in = LN(pre)
    ln128<<<Tn, 128>>>(pre, ain, an_g, an_b);
    // 3. up = x @ w_up^T                         [16384,2048]
    gemm_nt<0><<<dim3(16, 128, 1), blk>>>(x, w_up, Dn, nullptr, nullptr, 0,
                                          nullptr, nullptr, 0, up, Hn, nullptr, 0, 0, 0);
    // 4. hidden = silu(x @ w_gate^T) * up        [16384,2048]
    gemm_nt<1><<<dim3(16, 128, 1), blk>>>(x, w_gate, Dn, nullptr, nullptr, 0,
                                          nullptr, nullptr, 0, hid, Hn, up, 0, 0, 0);
    // 5. aout_raw = hidden @ w_post^T            [16384,128]
    gemm_nt<0><<<dim3(1, 128, 1), blk>>>(hid, w_post, Hn, nullptr, nullptr, 0,
                                         nullptr, nullptr, 0, aout, An, nullptr, 0, 0, 0);
    // 6. adapt_out = LN(aout_raw) in place
    ln128<<<Tn, 128>>>(aout, aout, an_g, an_b);
    // 7. aw = silu(clip(ain @ aout^T)) per batch [8,2048,2048]
    gemm_nt<2><<<dim3(16, 16, 8), blk>>>(ain, aout, An, nullptr, nullptr, 0,
                                         nullptr, nullptr, 0, aw, Sn, nullptr,
                                         (long)Sn * An, (long)Sn * An, (long)Sn * Sn);
    // 8. adapt01 = 0.1 * (aw @ ain) per batch    [8,2048,128]
    gemm_nn<3><<<dim3(1, 16, 8), blk>>>(aw, ain, adp, An, Sn,
                                        (long)Sn * Sn, (long)Sn * An, (long)Sn * An);
    // 9. wM = w_out @ w_eproj                    [1024,128]
    gemm_nn<0><<<dim3(1, 8, 1), blk>>>(w_out, w_eproj, wM, An, Hn, 0, 0, 0);
    // 10. wda = w_down @ w_aproj                 [1024,128]
    gemm_nn<0><<<dim3(1, 8, 1), blk>>>(w_down, w_aproj, wda, An, Hn, 0, 0, 0);
    // 11. aexp01 = 0.1 * LN(pre @ w_exp[last]^T) per token
    expert128<<<Tn, 128>>>(pre, ew, w_exp, eln_g, eln_b, aex);
    // 12. out = hidden@w_down^T + adapt01@wda^T + aexp01@wM^T   [16384,1024]
    gemm_nt<0><<<dim3(8, 128, 1), blk>>>(hid, w_down, Hn, adp, wda, An,
                                         aex, wM, An, out, Dn, nullptr, 0, 0, 0);
}

// round 5
// speedup vs baseline: 2.0325x; 2.0325x over previous
#include <cuda_runtime.h>
#include <math.h>
#include <stdint.h>

// Problem dims (fixed)
#define Tn 16384   // B*S tokens
#define Dn 1024
#define Hn 2048
#define An 128
#define En 8
#define Sn 2048
#define Bn 8

#define SPAD 136   // smem row pad (words): 136%32=8 -> frag loads conflict-free

// ---------------- scratch (device globals; no allocation allowed) -------------
__device__ float g_up[(size_t)Tn * Hn];
__device__ float g_hidden[(size_t)Tn * Hn];
__device__ float g_pre[(size_t)Tn * An];
__device__ float g_ain[(size_t)Tn * An];
__device__ float g_aout[(size_t)Tn * An];
__device__ float g_adapt[(size_t)Tn * An];
__device__ float g_aexp[(size_t)Tn * An];
__device__ float g_aw[(size_t)Bn * Sn * Sn];
__device__ float g_wM[Dn * An];
__device__ float g_wda[Dn * An];

__device__ __forceinline__ float silu_f(float x) { return x / (1.f + expf(-x)); }

__device__ __forceinline__ uint32_t f2tf(float f) {
    uint32_t r;
    asm("cvt.rna.tf32.f32 %0, %1;" : "=r"(r) : "f"(f));
    return r;
}

__device__ __forceinline__ void mma_tf32(float* c, const uint32_t* a, const uint32_t* b) {
    asm volatile(
        "mma.sync.aligned.m16n8k8.row.col.f32.tf32.tf32.f32 "
        "{%0,%1,%2,%3}, {%4,%5,%6,%7}, {%8,%9}, {%0,%1,%2,%3};"
        : "+f"(c[0]), "+f"(c[1]), "+f"(c[2]), "+f"(c[3])
        : "r"(a[0]), "r"(a[1]), "r"(a[2]), "r"(a[3]), "r"(b[0]), "r"(b[1]));
}

// ---------------- NT GEMM (tf32 tensor core) ----------------------------------
// C[m,n] = sum over (up to 3) segments A[m,:]·B[n,:]; A:[M,K] B:[N,K] row-major.
// Tile 128x128x32. 8 warps (2m x 4n), warp tile 64x32, m16n8k8 frags.
// EPI: 0=none, 1=silu(acc)*aux, 2=silu(clip(acc,-5,5)), 3=0.1*acc
template <int EPI>
__global__ __launch_bounds__(256, 2)
void gemm_nt_t(const float* __restrict__ A0, const float* __restrict__ B0, int K0,
               const float* __restrict__ A1, const float* __restrict__ B1, int K1,
               const float* __restrict__ A2, const float* __restrict__ B2, int K2,
               float* __restrict__ C, int N,
               const float* __restrict__ aux,
               long sA, long sB, long sC)
{
    __shared__ uint32_t As[32][SPAD];   // [k][m] tf32
    __shared__ uint32_t Bs[32][SPAD];   // [k][n] tf32
    const int bm = blockIdx.y << 7;
    const int bn = blockIdx.x << 7;
    const long z = blockIdx.z;
    const int tid = threadIdx.x;
    const int lane = tid & 31, warp = tid >> 5;
    const int wm = (warp & 1) << 6, wn = (warp >> 1) << 5;
    const int gid = lane >> 2, tig = lane & 3;
    const int ldr = tid >> 1;           // row 0..127
    const int ldk = (tid & 1) << 4;     // 0 or 16

    float acc[4][4][4];
#pragma unroll
    for (int mi = 0; mi < 4; mi++)
#pragma unroll
        for (int ni = 0; ni < 4; ni++)
#pragma unroll
            for (int q = 0; q < 4; q++) acc[mi][ni][q] = 0.f;

#pragma unroll 1
    for (int seg = 0; seg < 3; ++seg) {
        const float* A = (seg == 0) ? A0 + z * sA : ((seg == 1) ? A1 : A2);
        const float* B = (seg == 0) ? B0 + z * sB : ((seg == 1) ? B1 : B2);
        const int K = (seg == 0) ? K0 : ((seg == 1) ? K1 : K2);
        for (int kt = 0; kt < K; kt += 32) {
#pragma unroll
            for (int c = 0; c < 4; c++) {
                int k = ldk + c * 4;
                float4 v = *(const float4*)(A + (size_t)(bm + ldr) * K + kt + k);
                As[k + 0][ldr] = f2tf(v.x); As[k + 1][ldr] = f2tf(v.y);
                As[k + 2][ldr] = f2tf(v.z); As[k + 3][ldr] = f2tf(v.w);
                float4 w = *(const float4*)(B + (size_t)(bn + ldr) * K + kt + k);
                Bs[k + 0][ldr] = f2tf(w.x); Bs[k + 1][ldr] = f2tf(w.y);
                Bs[k + 2][ldr] = f2tf(w.z); Bs[k + 3][ldr] = f2tf(w.w);
            }
            __syncthreads();
#pragma unroll
            for (int ks = 0; ks < 4; ks++) {
                const int k0 = ks * 8 + tig;
                uint32_t a[4][4], b[4][2];
#pragma unroll
                for (int mi = 0; mi < 4; mi++) {
                    int m = wm + mi * 16 + gid;
                    a[mi][0] = As[k0][m];     a[mi][1] = As[k0][m + 8];
                    a[mi][2] = As[k0 + 4][m]; a[mi][3] = As[k0 + 4][m + 8];
                }
#pragma unroll
                for (int ni = 0; ni < 4; ni++) {
                    int n = wn + ni * 8 + gid;
                    b[ni][0] = Bs[k0][n]; b[ni][1] = Bs[k0 + 4][n];
                }
#pragma unroll
                for (int mi = 0; mi < 4; mi++)
#pragma unroll
                    for (int ni = 0; ni < 4; ni++)
                        mma_tf32(acc[mi][ni], a[mi], b[ni]);
            }
            __syncthreads();
        }
    }

    float* Cz = C + z * sC;
#pragma unroll
    for (int mi = 0; mi < 4; mi++) {
#pragma unroll
        for (int ni = 0; ni < 4; ni++) {
#pragma unroll
            for (int h = 0; h < 2; h++) {
                int row = bm + wm + mi * 16 + gid + h * 8;
                int col = bn + wn + ni * 8 + tig * 2;
                size_t off = (size_t)row * N + col;
                float v0 = acc[mi][ni][2 * h], v1 = acc[mi][ni][2 * h + 1];
                if (EPI == 1) { v0 = silu_f(v0) * aux[off]; v1 = silu_f(v1) * aux[off + 1]; }
                else if (EPI == 2) {
                    v0 = silu_f(fminf(fmaxf(v0, -5.f), 5.f));
                    v1 = silu_f(fminf(fmaxf(v1, -5.f), 5.f));
                }
                else if (EPI == 3) { v0 *= 0.1f; v1 *= 0.1f; }
                *(float2*)(Cz + off) = make_float2(v0, v1);
            }
        }
    }
}

// ---------------- NN GEMM (tf32 tensor core) ----------------------------------
// C[m,n] = sum_k A[m,k]*B[k,n]; A:[M,K], B:[K,N] row-major. Same tiling.
template <int EPI>
__global__ __launch_bounds__(256, 2)
void gemm_nn_t(const float* __restrict__ A, const float* __restrict__ B,
               float* __restrict__ C, int N, int K,
               long sA, long sB, long sC)
{
    __shared__ uint32_t As[32][SPAD];   // [k][m]
    __shared__ uint32_t Bs[32][SPAD];   // [k][n]
    const int bm = blockIdx.y << 7;
    const int bn = blockIdx.x << 7;
    const long z = blockIdx.z;
    const int tid = threadIdx.x;
    const int lane = tid & 31, warp = tid >> 5;
    const int wm = (warp & 1) << 6, wn = (warp >> 1) << 5;
    const int gid = lane >> 2, tig = lane & 3;
    const int ldr = tid >> 1;
    const int ldk = (tid & 1) << 4;
    const int bk = tid >> 3;            // B loader: k row 0..31
    const int bnc = (tid & 7) << 4;     // base n offset (x4 chunks of 4)

    const float* Az = A + z * sA;
    const float* Bz = B + z * sB;

    float acc[4][4][4];
#pragma unroll
    for (int mi = 0; mi < 4; mi++)
#pragma unroll
        for (int ni = 0; ni < 4; ni++)
#pragma unroll
            for (int q = 0; q < 4; q++) acc[mi][ni][q] = 0.f;

    for (int kt = 0; kt < K; kt += 32) {
#pragma unroll
        for (int c = 0; c < 4; c++) {
            int k = ldk + c * 4;
            float4 v = *(const float4*)(Az + (size_t)(bm + ldr) * K + kt + k);
            As[k + 0][ldr] = f2tf(v.x); As[k + 1][ldr] = f2tf(v.y);
            As[k + 2][ldr] = f2tf(v.z); As[k + 3][ldr] = f2tf(v.w);
            int n0 = bnc + c * 4;
            float4 w = *(const float4*)(Bz + (size_t)(kt + bk) * N + bn + n0);
            *(uint4*)&Bs[bk][n0] = make_uint4(f2tf(w.x), f2tf(w.y), f2tf(w.z), f2tf(w.w));
        }
        __syncthreads();
#pragma unroll
        for (int ks = 0; ks < 4; ks++) {
            const int k0 = ks * 8 + tig;
            uint32_t a[4][4], b[4][2];
#pragma unroll
            for (int mi = 0; mi < 4; mi++) {
                int m = wm + mi * 16 + gid;
                a[mi][0] = As[k0][m];     a[mi][1] = As[k0][m + 8];
                a[mi][2] = As[k0 + 4][m]; a[mi][3] = As[k0 + 4][m + 8];
            }
#pragma unroll
            for (int ni = 0; ni < 4; ni++) {
                int n = wn + ni * 8 + gid;
                b[ni][0] = Bs[k0][n]; b[ni][1] = Bs[k0 + 4][n];
            }
#pragma unroll
            for (int mi = 0; mi < 4; mi++)
#pragma unroll
                for (int ni = 0; ni < 4; ni++)
                    mma_tf32(acc[mi][ni], a[mi], b[ni]);
        }
        __syncthreads();
    }

    float* Cz = C + z * sC;
#pragma unroll
    for (int mi = 0; mi < 4; mi++) {
#pragma unroll
        for (int ni = 0; ni < 4; ni++) {
#pragma unroll
            for (int h = 0; h < 2; h++) {
                int row = bm + wm + mi * 16 + gid + h * 8;
                int col = bn + wn + ni * 8 + tig * 2;
                size_t off = (size_t)row * N + col;
                float v0 = acc[mi][ni][2 * h], v1 = acc[mi][ni][2 * h + 1];
                if (EPI == 3) { v0 *= 0.1f; v1 *= 0.1f; }
                *(float2*)(Cz + off) = make_float2(v0, v1);
            }
        }
    }
}

// ---------------- LayerNorm over last dim (A=128), one token per block --------
__global__ void ln128(const float* __restrict__ in, float* __restrict__ out,
                      const float* __restrict__ g, const float* __restrict__ b)
{
    __shared__ float red[128];
    const int tok = blockIdx.x, tid = threadIdx.x;
    float x = in[(size_t)tok * 128 + tid];
    red[tid] = x; __syncthreads();
#pragma unroll
    for (int s = 64; s > 0; s >>= 1) { if (tid < s) red[tid] += red[tid + s]; __syncthreads(); }
    float mean = red[0] * (1.f / 128.f);
    __syncthreads();
    float d = x - mean;
    red[tid] = d * d; __syncthreads();
#pragma unroll
    for (int s = 64; s > 0; s >>= 1) { if (tid < s) red[tid] += red[tid + s]; __syncthreads(); }
    float var = red[0] * (1.f / 128.f);
    out[(size_t)tok * 128 + tid] = d * rsqrtf(var + 1e-5f) * g[tid] + b[tid];
}

// ---------------- expert path: last selected expert, matvec + LN, 0.1 scale ---
__global__ void expert128(const float* __restrict__ pre, const float* __restrict__ ew,
                          const float* __restrict__ w_exp, const float* __restrict__ eg,
                          const float* __restrict__ eb, float* __restrict__ out)
{
    __shared__ float sp[128];
    __shared__ float red[128];
    const int tok = blockIdx.x, tid = threadIdx.x;
    int sel = -1;
#pragma unroll
    for (int i = 0; i < 8; i++)
        if (ew[(size_t)tok * 8 + i] > 0.f) sel = i;   // later experts win
    if (sel < 0) { out[(size_t)tok * 128 + tid] = 0.f; return; }

    sp[tid] = pre[(size_t)tok * 128 + tid];
    __syncthreads();
    const float* wr = w_exp + ((size_t)sel * 128 + tid) * 128;
    float acc = 0.f;
#pragma unroll 8
    for (int a = 0; a < 128; a++) acc = fmaf(sp[a], wr[a], acc);

    red[tid] = acc; __syncthreads();
#pragma unroll
    for (int s = 64; s > 0; s >>= 1) { if (tid < s) red[tid] += red[tid + s]; __syncthreads(); }
    float mean = red[0] * (1.f / 128.f);
    __syncthreads();
    float d = acc - mean;
    red[tid] = d * d; __syncthreads();
#pragma unroll
    for (int s = 64; s > 0; s >>= 1) { if (tid < s) red[tid] += red[tid + s]; __syncthreads(); }
    float var = red[0] * (1.f / 128.f);
    out[(size_t)tok * 128 + tid] =
        0.1f * (d * rsqrtf(var + 1e-5f) * eg[sel * 128 + tid] + eb[sel * 128 + tid]);
}

// ---------------- launch ------------------------------------------------------
extern "C" void kernel_launch(void* const* d_in, const int* in_sizes, int n_in,
                              void* d_out, int out_size)
{
    const float* x       = (const float*)d_in[0];
    const float* ew      = (const float*)d_in[1];
    const float* w_up    = (const float*)d_in[2];
    const float* w_gate  = (const float*)d_in[3];
    const float* w_down  = (const float*)d_in[4];
    const float* w_pre   = (const float*)d_in[5];
    const float* w_post  = (const float*)d_in[6];
    const float* an_g    = (const float*)d_in[7];
    const float* an_b    = (const float*)d_in[8];
    const float* w_aproj = (const float*)d_in[9];
    const float* w_exp   = (const float*)d_in[10];
    const float* eln_g   = (const float*)d_in[11];
    const float* eln_b   = (const float*)d_in[12];
    const float* w_eproj = (const float*)d_in[13];
    const float* w_out   = (const float*)d_in[14];
    float* out = (float*)d_out;

    float *up, *hid, *pre, *ain, *aout, *adp, *aex, *aw, *wM, *wda;
    cudaGetSymbolAddress((void**)&up,   g_up);
    cudaGetSymbolAddress((void**)&hid,  g_hidden);
    cudaGetSymbolAddress((void**)&pre,  g_pre);
    cudaGetSymbolAddress((void**)&ain,  g_ain);
    cudaGetSymbolAddress((void**)&aout, g_aout);
    cudaGetSymbolAddress((void**)&adp,  g_adapt);
    cudaGetSymbolAddress((void**)&aex,  g_aexp);
    cudaGetSymbolAddress((void**)&aw,   g_aw);
    cudaGetSymbolAddress((void**)&wM,   g_wM);
    cudaGetSymbolAddress((void**)&wda,  g_wda);

    const dim3 blk(256);

    // 1. pre = x @ w_pre^T                       [16384,128]
    gemm_nt_t<0><<<dim3(1, 128, 1), blk>>>(x, w_pre, Dn, nullptr, nullptr, 0,
                                           nullptr, nullptr, 0, pre, An, nullptr, 0, 0, 0);
    // 2. adapt_in = LN(pre)
    ln128<<<Tn, 128>>>(pre, ain, an_g, an_b);
    // 3. up = x @ w_up^T                         [16384,2048]
    gemm_nt_t<0><<<dim3(16, 128, 1), blk>>>(x, w_up, Dn, nullptr, nullptr, 0,
                                            nullptr, nullptr, 0, up, Hn, nullptr, 0, 0, 0);
    // 4. hidden = silu(x @ w_gate^T) * up        [16384,2048]
    gemm_nt_t<1><<<dim3(16, 128, 1), blk>>>(x, w_gate, Dn, nullptr, nullptr, 0,
                                            nullptr, nullptr, 0, hid, Hn, up, 0, 0, 0);
    // 5. aout_raw = hidden @ w_post^T            [16384,128]
    gemm_nt_t<0><<<dim3(1, 128, 1), blk>>>(hid, w_post, Hn, nullptr, nullptr, 0,
                                           nullptr, nullptr, 0, aout, An, nullptr, 0, 0, 0);
    // 6. adapt_out = LN(aout_raw) in place
    ln128<<<Tn, 128>>>(aout, aout, an_g, an_b);
    // 7. aw = silu(clip(ain @ aout^T)) per batch [8,2048,2048]
    gemm_nt_t<2><<<dim3(16, 16, 8), blk>>>(ain, aout, An, nullptr, nullptr, 0,
                                           nullptr, nullptr, 0, aw, Sn, nullptr,
                                           (long)Sn * An, (long)Sn * An, (long)Sn * Sn);
    // 8. adapt01 = 0.1 * (aw @ ain) per batch    [8,2048,128]
    gemm_nn_t<3><<<dim3(1, 16, 8), blk>>>(aw, ain, adp, An, Sn,
                                          (long)Sn * Sn, (long)Sn * An, (long)Sn * An);
    // 9. wM = w_out @ w_eproj                    [1024,128]
    gemm_nn_t<0><<<dim3(1, 8, 1), blk>>>(w_out, w_eproj, wM, An, Hn, 0, 0, 0);
    // 10. wda = w_down @ w_aproj                 [1024,128]
    gemm_nn_t<0><<<dim3(1, 8, 1), blk>>>(w_down, w_aproj, wda, An, Hn, 0, 0, 0);
    // 11. aexp01 = 0.1 * LN(pre @ w_exp[last]^T) per token
    expert128<<<Tn, 128>>>(pre, ew, w_exp, eln_g, eln_b, aex);
    // 12. out = hidden@w_down^T + adapt01@wda^T + aexp01@wM^T   [16384,1024]
    gemm_nt_t<0><<<dim3(8, 128, 1), blk>>>(hid, w_down, Hn, adp, wda, An,
                                           aex, wM, An, out, Dn, nullptr, 0, 0, 0);
}